// round 7
// baseline (speedup 1.0000x reference)
#include <cuda_runtime.h>
#include <cuda_bf16.h>
#include <cuda_fp16.h>
#include <cstdint>

// ---------------------------------------------------------------------------
// EdgeClassNet: node MLP (fp32 FFMA2) + fused 9-layer edge MLP on warp-level
// fp16 mma.sync. R7: R5 shape (256 thr / 128 edges / RING=4) but per-chunk
// block syncs replaced by a producer-consumer mbarrier ring; warps free-run
// within a layer (drift <= 3 chunks), syncing only at layer boundaries.
// ---------------------------------------------------------------------------

constexpr int DN   = 256;   // node input dim
constexpr int IN   = 128;   // node hidden dim
constexpr int EA   = 16;
constexpr int NOUT = 3;
constexpr int TMN  = 64;    // node kernel tile
constexpr int KCN  = 16;

constexpr int MAXN = 65536;
constexpr int MAXE = 262144;

// 73 weight chunks: layer0 = 9 chunks of K<=32, layers 1..8 = 8 chunks each.
// Each chunk image: [256 n][40 k] fp16 = 20480 B.
constexpr int NCHUNK = 73;
constexpr int WCH    = 20480;
constexpr int RING   = 4;

__device__ float g_hnode[MAXN * IN];
__device__ int   g_ei[2 * MAXE];
__device__ int   g_is64;
__device__ __align__(16) unsigned char g_wpack[NCHUNK * WCH];

// ======================= small utility kernels =============================
__global__ void detect_kernel(const int* __restrict__ ei_raw) {
    __shared__ int cnt;
    if (threadIdx.x == 0) cnt = 0;
    __syncthreads();
    if (ei_raw[2 * threadIdx.x + 1] != 0) atomicAdd(&cnt, 1);
    __syncthreads();
    if (threadIdx.x == 0) g_is64 = (cnt == 0) ? 1 : 0;
}
__global__ void convert_kernel(const int* __restrict__ ei_raw, int n2e) {
    int i = blockIdx.x * blockDim.x + threadIdx.x;
    if (i >= n2e) return;
    g_ei[i] = g_is64 ? ei_raw[2 * i] : ei_raw[i];
}
// pack weights into per-chunk SMEM images (transposed to [n][k], fp16)
__global__ void prep_pack(const float* __restrict__ W0,
                          const float* __restrict__ Wmid) {
    int idx = blockIdx.x * 256 + threadIdx.x;       // over 73*256*40
    if (idx >= NCHUNK * 256 * 40) return;
    int klocal = idx % 40;
    int n  = (idx / 40) & 255;
    int ch = idx / (40 * 256);
    int L, cc;
    if (ch < 9) { L = 0; cc = ch; } else { L = 1 + (ch - 9) / 8; cc = (ch - 9) & 7; }
    int k = cc * 32 + klocal;
    int K = (L == 0) ? 272 : 256;
    float w = 0.f;
    if (klocal < 32 && k < K)
        w = (L == 0) ? W0[k * 256 + n] : Wmid[(L - 1) * 65536 + k * 256 + n];
    *(__half*)(g_wpack + (size_t)ch * WCH + n * 80 + klocal * 2) = __float2half_rn(w);
}

// ======================= PTX helpers =======================================
__device__ __forceinline__ uint32_t smem_u32(const void* p) {
    uint32_t a;
    asm("{ .reg .u64 t; cvta.to.shared.u64 t, %1; cvt.u32.u64 %0, t; }"
        : "=r"(a) : "l"(p));
    return a;
}
__device__ __forceinline__ void cp16b(char* dst, const char* src) {
    unsigned u = (unsigned)__cvta_generic_to_shared(dst);
    asm volatile("cp.async.cg.shared.global [%0], [%1], 16;" :: "r"(u), "l"(src));
}
__device__ __forceinline__ void cp_commit() { asm volatile("cp.async.commit_group;"); }
template<int N> __device__ __forceinline__ void cp_wait() {
    asm volatile("cp.async.wait_group %0;" :: "n"(N));
}
__device__ __forceinline__ void mbar_init(uint32_t a, uint32_t cnt) {
    asm volatile("mbarrier.init.shared.b64 [%0], %1;" :: "r"(a), "r"(cnt) : "memory");
}
__device__ __forceinline__ void mbar_expect_tx(uint32_t a, uint32_t bytes) {
    asm volatile("mbarrier.arrive.expect_tx.shared.b64 _, [%0], %1;"
                 :: "r"(a), "r"(bytes) : "memory");
}
__device__ __forceinline__ void mbar_arrive(uint32_t a) {
    asm volatile("mbarrier.arrive.shared.b64 _, [%0];" :: "r"(a) : "memory");
}
__device__ __forceinline__ void bulk_g2s(uint32_t dst, const void* src,
                                         uint32_t bytes, uint32_t mbar) {
    asm volatile(
        "cp.async.bulk.shared::cluster.global.mbarrier::complete_tx::bytes "
        "[%0], [%1], %2, [%3];"
        :: "r"(dst), "l"(src), "r"(bytes), "r"(mbar) : "memory");
}
__device__ __forceinline__ void mbar_wait(uint32_t mbar, uint32_t parity) {
    asm volatile(
        "{\n\t.reg .pred P1;\n\t"
        "WAIT_LOOP_%=:\n\t"
        "mbarrier.try_wait.parity.acquire.cta.shared::cta.b64 P1, [%0], %1, 0x989680;\n\t"
        "@P1 bra.uni WAIT_DONE_%=;\n\t"
        "bra.uni WAIT_LOOP_%=;\n\t"
        "WAIT_DONE_%=:\n\t}"
        :: "r"(mbar), "r"(parity) : "memory");
}
__device__ __forceinline__ void ldm_x4(uint32_t* r, uint32_t addr) {
    asm volatile("ldmatrix.sync.aligned.m8n8.x4.shared.b16 {%0,%1,%2,%3}, [%4];"
                 : "=r"(r[0]), "=r"(r[1]), "=r"(r[2]), "=r"(r[3]) : "r"(addr));
}
__device__ __forceinline__ void mma16816(float* c, const uint32_t* a,
                                         uint32_t b0, uint32_t b1) {
    asm volatile(
        "mma.sync.aligned.m16n8k16.row.col.f32.f16.f16.f32 "
        "{%0,%1,%2,%3}, {%4,%5,%6,%7}, {%8,%9}, {%0,%1,%2,%3};"
        : "+f"(c[0]), "+f"(c[1]), "+f"(c[2]), "+f"(c[3])
        : "r"(a[0]), "r"(a[1]), "r"(a[2]), "r"(a[3]), "r"(b0), "r"(b1));
}
__device__ __forceinline__ uint32_t h2(float v0, float v1) {
    __half2 h = __floats2half2_rn(v0, v1);
    return *(uint32_t*)&h;
}

// ======================= node MLP (FFMA2 path, known good) =================
__device__ __forceinline__ unsigned long long pack2(float x) {
    unsigned long long r; unsigned v = __float_as_uint(x);
    asm("mov.b64 %0, {%1,%2};" : "=l"(r) : "r"(v), "r"(v));
    return r;
}
__device__ __forceinline__ void ffma2(unsigned long long& c, unsigned long long a,
                                      unsigned long long b) {
    asm("fma.rn.f32x2 %0, %1, %2, %0;" : "+l"(c) : "l"(a), "l"(b));
}
__device__ __forceinline__ float2 unpack2(unsigned long long v) {
    unsigned lo, hi;
    asm("mov.b64 {%0,%1}, %2;" : "=r"(lo), "=r"(hi) : "l"(v));
    float2 f; f.x = __uint_as_float(lo); f.y = __uint_as_float(hi);
    return f;
}
__device__ __forceinline__ void cp16f(float* dst, const float* src) {
    cp16b((char*)dst, (const char*)src);
}

constexpr int XSTR   = 260;
constexpr int A_SMEM = (TMN * XSTR + 2 * KCN * IN) * 4;

__global__ void __launch_bounds__(256, 2)
node_mlp_kernel(const float* __restrict__ x, const float* __restrict__ Wx,
                const float* __restrict__ bx)
{
    extern __shared__ float sm[];
    float* abuf = sm;
    float* bbuf = sm + TMN * XSTR;
    const int tid = threadIdx.x;
    const long long r0 = (long long)blockIdx.x * TMN;
    {
        int e = tid >> 2, q = tid & 3;
        const float* src = x + (r0 + e) * DN + q * 64;
        float* dst = abuf + e * XSTR + q * 64;
#pragma unroll
        for (int i = 0; i < 16; i++) cp16f(dst + i * 4, src + i * 4);
        cp_commit();
    }
    const int tr = tid >> 4, tc = tid & 15;
    const int m0 = tr * 4;
    unsigned long long acc[4][4];
#pragma unroll
    for (int i = 0; i < 4; i++)
#pragma unroll
        for (int j = 0; j < 4; j++) acc[i][j] = 0ull;
    constexpr int CHUNK = KCN * IN;
    {
#pragma unroll
        for (int i = 0; i < 2; i++)
            cp16f(bbuf + (tid + i * 256) * 4, Wx + (tid + i * 256) * 4);
        cp_commit();
    }
    const int nk = DN / KCN;
    for (int kc = 0; kc < nk; kc++) {
        if (kc + 1 < nk) {
            const float* src = Wx + (long long)(kc + 1) * CHUNK;
            float* dst = bbuf + ((kc + 1) & 1) * CHUNK;
#pragma unroll
            for (int i = 0; i < 2; i++)
                cp16f(dst + (tid + i * 256) * 4, src + (tid + i * 256) * 4);
            cp_commit();
            cp_wait<1>();
        } else cp_wait<0>();
        __syncthreads();
        const float* Bs = bbuf + (kc & 1) * CHUNK;
        const float* As = abuf + kc * KCN;
#pragma unroll
        for (int kk = 0; kk < KCN; kk++) {
            unsigned long long breg[4];
            const float* brow = Bs + kk * IN + 2 * tc;
#pragma unroll
            for (int j = 0; j < 4; j++)
                breg[j] = *(const unsigned long long*)(brow + 32 * j);
#pragma unroll
            for (int i = 0; i < 4; i++) {
                unsigned long long aa = pack2(As[(m0 + i) * XSTR + kk]);
#pragma unroll
                for (int j = 0; j < 4; j++) ffma2(acc[i][j], aa, breg[j]);
            }
        }
        __syncthreads();
    }
    float* gout = g_hnode + r0 * IN;
#pragma unroll
    for (int i = 0; i < 4; i++)
#pragma unroll
        for (int j = 0; j < 4; j++) {
            int n = 2 * tc + 32 * j;
            float2 v = unpack2(acc[i][j]);
            v.x += bx[n]; v.y += bx[n + 1];
            v.x = fmaxf(v.x, 0.01f * v.x);
            v.y = fmaxf(v.y, 0.01f * v.y);
            *(float2*)(gout + (long long)(m0 + i) * IN + n) = v;
        }
}

// ======================= edge MLP on fp16 mma.sync =========================
// SMEM layout (bytes):
constexpr int ASTRB   = 560;                     // A row stride: 280 fp16
constexpr int OFF_W   = 128 * ASTRB;             // 71680 (ring of 4 chunk bufs)
constexpr int OFF_PT  = OFF_W;                   // classifier partials (reuse)
constexpr int OFF_MBF = OFF_W + RING * WCH;      // 153600: full barriers (4)
constexpr int OFF_MBE = OFF_MBF + 32;            // empty barriers (4)
constexpr int SMEM_E  = OFF_MBE + 32;

__global__ void __launch_bounds__(256, 1)
edge_hmma_kernel(const float* __restrict__ eattr,
                 const float* __restrict__ b0, const float* __restrict__ bmid,
                 const float* __restrict__ Wlast, const float* __restrict__ blast,
                 float* __restrict__ out, int E)
{
    extern __shared__ char smc[];
    const uint32_t sbase = smem_u32(smc);
    const int tid = threadIdx.x, wid = tid >> 5, lane = tid & 31;
    const int mg = wid >> 2, ng = wid & 3;        // 2 x 4 warp grid
    const int RB = 64 * mg, CB = 64 * ng;
    const long long e0 = (long long)blockIdx.x * 128;

    if (tid == 0)
        for (int i = 0; i < RING; i++) {
            mbar_init(sbase + OFF_MBF + i * 8, 1);   // full: tx-based
            mbar_init(sbase + OFF_MBE + i * 8, 8);   // empty: 8 warp arrivals
        }
    __syncthreads();
    if (tid == 0) {
        for (int ci = 0; ci < RING; ci++) {
            uint32_t mb = sbase + OFF_MBF + ci * 8;
            mbar_expect_tx(mb, WCH);
            bulk_g2s(sbase + OFF_W + ci * WCH, g_wpack + (size_t)ci * WCH, WCH, mb);
        }
    }

    // ---------------- gather ef -> A plane (fp16) ---------------------------
    {
        int e = tid >> 1, half = tid & 1;
        long long ge = e0 + e;
        int ridx = g_ei[ge];
        int cidx = g_ei[(long long)E + ge];
        const float4* hr4 = (const float4*)(g_hnode + (long long)ridx * IN);
        const float4* hc4 = (const float4*)(g_hnode + (long long)cidx * IN);
        const float4* ea4 = (const float4*)(eattr + ge * EA);
        int ch = half * 136;
#pragma unroll 2
        for (int g = 0; g < 34; g++) {
            int c = ch + 4 * g;
            float4 f = (c < 128) ? hr4[c >> 2]
                     : (c < 256) ? hc4[(c - 128) >> 2]
                                 : ea4[(c - 256) >> 2];
            char* pA = smc + e * ASTRB + c * 2;
            *(uint32_t*)(pA)     = h2(f.x, f.y);
            *(uint32_t*)(pA + 4) = h2(f.z, f.w);
        }
    }
    __syncthreads();

    // ---------------- per-thread invariant addresses ------------------------
    const int i7 = lane & 7;
    const int rowOff  = ((lane >> 3) & 1) * 8 + i7;
    const int aColOff = (lane >= 16) ? 16 : 0;            // bytes
    uint32_t aB[4];
#pragma unroll
    for (int i = 0; i < 4; i++)
        aB[i] = sbase + (uint32_t)(RB + 16 * i + rowOff) * ASTRB + aColOff;
    const int nIdx  = CB + ((lane >= 16) ? 8 : 0) + i7;
    const int bkOff = ((lane >> 3) & 1) * 16;             // bytes
    uint32_t bB[4];
#pragma unroll
    for (int j = 0; j < 4; j++) bB[j] = (uint32_t)(nIdx + 16 * j) * 80 + bkOff;

    float c[4][8][4];
#pragma unroll
    for (int i = 0; i < 4; i++)
#pragma unroll
        for (int j = 0; j < 8; j++)
#pragma unroll
            for (int q = 0; q < 4; q++) c[i][j][q] = 0.f;

    int chunkIdx = 0;

#pragma unroll 1
    for (int L = 0; L < 9; L++) {
        const int nch = (L == 0) ? 9 : 8;
#pragma unroll 1
        for (int cI = 0; cI < nch; cI++) {
            const int slot = chunkIdx & (RING - 1);
            const uint32_t par = (uint32_t)((chunkIdx >> 2) & 1);
            mbar_wait(sbase + OFF_MBF + slot * 8, par);
            const uint32_t wb = sbase + OFF_W + slot * WCH;
            const int steps = (L == 0 && cI == 8) ? 1 : 2;
            const int kbB = cI * 64;                       // A byte offset of chunk
#pragma unroll 1
            for (int s = 0; s < steps; s++) {
                const int kl = kbB + s * 32;
                uint32_t b[4][4], a[4][4];
#pragma unroll
                for (int j = 0; j < 4; j++) ldm_x4(b[j], wb + bB[j] + s * 32);
#pragma unroll
                for (int i = 0; i < 4; i++) ldm_x4(a[i], aB[i] + kl);
#pragma unroll
                for (int i = 0; i < 4; i++)
#pragma unroll
                    for (int j = 0; j < 4; j++) {
                        mma16816(c[i][2 * j],     a[i], b[j][0], b[j][1]);
                        mma16816(c[i][2 * j + 1], a[i], b[j][2], b[j][3]);
                    }
            }
            // consumed: one arrive per warp; rotating producer refills the slot
            if (lane == 0) {
                mbar_arrive(sbase + OFF_MBE + slot * 8);
                if (wid == (chunkIdx & 7) && chunkIdx + RING < NCHUNK) {
                    mbar_wait(sbase + OFF_MBE + slot * 8, par);
                    const uint32_t mbf = sbase + OFF_MBF + slot * 8;
                    mbar_expect_tx(mbf, WCH);
                    bulk_g2s(sbase + OFF_W + slot * WCH,
                             g_wpack + (size_t)(chunkIdx + RING) * WCH, WCH, mbf);
                }
            }
            chunkIdx++;
        }

        if (L < 8) {
            __syncthreads();   // all warps done reading A for this layer
            // epilogue: leaky(D + bias) -> fp16 -> A plane; zero C
            const float* bias = (L == 0) ? b0 : bmid + (L - 1) * 256;
#pragma unroll
            for (int i = 0; i < 4; i++) {
                const int row0 = RB + 16 * i + (lane >> 2);
#pragma unroll
                for (int j = 0; j < 8; j++) {
                    const int col = CB + 8 * j + 2 * (lane & 3);
                    float2 bb = __ldg((const float2*)(bias + col));
                    float v0 = c[i][j][0] + bb.x, v1 = c[i][j][1] + bb.y;
                    float v2 = c[i][j][2] + bb.x, v3 = c[i][j][3] + bb.y;
                    v0 = fmaxf(v0, 0.01f * v0); v1 = fmaxf(v1, 0.01f * v1);
                    v2 = fmaxf(v2, 0.01f * v2); v3 = fmaxf(v3, 0.01f * v3);
                    char* p0 = smc + row0 * ASTRB + col * 2;
                    *(uint32_t*)(p0)             = h2(v0, v1);
                    *(uint32_t*)(p0 + 8 * ASTRB) = h2(v2, v3);
                    c[i][j][0] = 0.f; c[i][j][1] = 0.f;
                    c[i][j][2] = 0.f; c[i][j][3] = 0.f;
                }
            }
            __syncthreads();   // A plane ready for next layer
        }
    }

    // ---------------- classifier + log_softmax ------------------------------
    __syncthreads();
    {
        const float* bias = bmid + 7 * 256;
        float p[4][2][3];
#pragma unroll
        for (int i = 0; i < 4; i++)
#pragma unroll
            for (int h = 0; h < 2; h++)
                p[i][h][0] = p[i][h][1] = p[i][h][2] = 0.f;
#pragma unroll
        for (int i = 0; i < 4; i++) {
#pragma unroll
            for (int j = 0; j < 8; j++) {
                const int col = CB + 8 * j + 2 * (lane & 3);
                float2 bb = __ldg((const float2*)(bias + col));
                float v0 = c[i][j][0] + bb.x, v1 = c[i][j][1] + bb.y;
                float v2 = c[i][j][2] + bb.x, v3 = c[i][j][3] + bb.y;
                v0 = fmaxf(v0, 0.01f * v0); v1 = fmaxf(v1, 0.01f * v1);
                v2 = fmaxf(v2, 0.01f * v2); v3 = fmaxf(v3, 0.01f * v3);
                const float* w0 = Wlast + col * 3;
#pragma unroll
                for (int k = 0; k < 3; k++) {
                    float wa = __ldg(w0 + k), wb2 = __ldg(w0 + 3 + k);
                    p[i][0][k] = fmaf(v0, wa, fmaf(v1, wb2, p[i][0][k]));
                    p[i][1][k] = fmaf(v2, wa, fmaf(v3, wb2, p[i][1][k]));
                }
            }
        }
#pragma unroll
        for (int i = 0; i < 4; i++)
#pragma unroll
            for (int h = 0; h < 2; h++)
#pragma unroll
                for (int k = 0; k < 3; k++) {
                    float v = p[i][h][k];
                    v += __shfl_xor_sync(0xffffffffu, v, 1);
                    v += __shfl_xor_sync(0xffffffffu, v, 2);
                    p[i][h][k] = v;
                }
        float* pt = (float*)(smc + OFF_PT);   // [128 rows][4 ng][3]
        if ((lane & 3) == 0) {
#pragma unroll
            for (int i = 0; i < 4; i++)
#pragma unroll
                for (int h = 0; h < 2; h++) {
                    int row = RB + 16 * i + (lane >> 2) + 8 * h;
#pragma unroll
                    for (int k = 0; k < 3; k++)
                        pt[(row * 4 + ng) * 3 + k] = p[i][h][k];
                }
        }
    }
    __syncthreads();
    if (tid < 128) {
        const float* pt = (const float*)(smc + OFF_PT);
        float l[3];
#pragma unroll
        for (int k = 0; k < 3; k++) {
            float s = __ldg(blast + k);
#pragma unroll
            for (int g = 0; g < 4; g++) s += pt[(tid * 4 + g) * 3 + k];
            l[k] = s;
        }
        float mx  = fmaxf(l[0], fmaxf(l[1], l[2]));
        float lse = mx + logf(expf(l[0] - mx) + expf(l[1] - mx) + expf(l[2] - mx));
        float* o = out + (e0 + tid) * NOUT;
        o[0] = l[0] - lse; o[1] = l[1] - lse; o[2] = l[2] - lse;
    }
}

// ===========================================================================
extern "C" void kernel_launch(void* const* d_in, const int* in_sizes, int n_in,
                              void* d_out, int out_size)
{
    const float* x      = (const float*)d_in[0];
    const int*   ei_raw = (const int*)d_in[1];
    const float* eattr  = (const float*)d_in[2];
    const float* Wx     = (const float*)d_in[3];
    const float* bx     = (const float*)d_in[4];
    const float* W0     = (const float*)d_in[5];
    const float* b0     = (const float*)d_in[6];
    const float* Wmid   = (const float*)d_in[7];
    const float* bmid   = (const float*)d_in[8];
    const float* Wlast  = (const float*)d_in[9];
    const float* blast  = (const float*)d_in[10];
    float* out = (float*)d_out;

    const int N  = in_sizes[0] / DN;
    const int E  = in_sizes[2] / EA;
    const int n2 = 2 * E;

    cudaFuncSetAttribute(node_mlp_kernel,
                         cudaFuncAttributeMaxDynamicSharedMemorySize, A_SMEM);
    cudaFuncSetAttribute(edge_hmma_kernel,
                         cudaFuncAttributeMaxDynamicSharedMemorySize, SMEM_E);

    detect_kernel<<<1, 256>>>(ei_raw);
    convert_kernel<<<(n2 + 255) / 256, 256>>>(ei_raw, n2);
    prep_pack<<<(NCHUNK * 256 * 40 + 255) / 256, 256>>>(W0, Wmid);
    node_mlp_kernel<<<N / TMN, 256, A_SMEM>>>(x, Wx, bx);
    edge_hmma_kernel<<<E / 128, 256, SMEM_E>>>(eattr, b0, bmid, Wlast, blast,
                                               out, E);
}

// round 8
// speedup vs baseline: 1.6199x; 1.6199x over previous
#include <cuda_runtime.h>
#include <cuda_bf16.h>
#include <cuda_fp16.h>
#include <cstdint>

// ---------------------------------------------------------------------------
// EdgeClassNet: node MLP (fp32 FFMA2) + fused 9-layer edge MLP on warp-level
// fp16 mma.sync. R8: R5 structure + software-pipelined fragment loads
// (B double-buffered across k16 steps and across chunks; A just-in-time).
// ---------------------------------------------------------------------------

constexpr int DN   = 256;   // node input dim
constexpr int IN   = 128;   // node hidden dim
constexpr int EA   = 16;
constexpr int NOUT = 3;
constexpr int TMN  = 64;    // node kernel tile
constexpr int KCN  = 16;

constexpr int MAXN = 65536;
constexpr int MAXE = 262144;

// 73 weight chunks: layer0 = 9 chunks of K<=32, layers 1..8 = 8 chunks each.
// Each chunk image: [256 n][40 k] fp16 = 20480 B.
constexpr int NCHUNK = 73;
constexpr int WCH    = 20480;
constexpr int RING   = 4;

__device__ float g_hnode[MAXN * IN];
__device__ int   g_ei[2 * MAXE];
__device__ int   g_is64;
__device__ __align__(16) unsigned char g_wpack[NCHUNK * WCH];

// ======================= small utility kernels =============================
__global__ void detect_kernel(const int* __restrict__ ei_raw) {
    __shared__ int cnt;
    if (threadIdx.x == 0) cnt = 0;
    __syncthreads();
    if (ei_raw[2 * threadIdx.x + 1] != 0) atomicAdd(&cnt, 1);
    __syncthreads();
    if (threadIdx.x == 0) g_is64 = (cnt == 0) ? 1 : 0;
}
__global__ void convert_kernel(const int* __restrict__ ei_raw, int n2e) {
    int i = blockIdx.x * blockDim.x + threadIdx.x;
    if (i >= n2e) return;
    g_ei[i] = g_is64 ? ei_raw[2 * i] : ei_raw[i];
}
// pack weights into per-chunk SMEM images (transposed to [n][k], fp16)
__global__ void prep_pack(const float* __restrict__ W0,
                          const float* __restrict__ Wmid) {
    int idx = blockIdx.x * 256 + threadIdx.x;       // over 73*256*40
    if (idx >= NCHUNK * 256 * 40) return;
    int klocal = idx % 40;
    int n  = (idx / 40) & 255;
    int ch = idx / (40 * 256);
    int L, cc;
    if (ch < 9) { L = 0; cc = ch; } else { L = 1 + (ch - 9) / 8; cc = (ch - 9) & 7; }
    int k = cc * 32 + klocal;
    int K = (L == 0) ? 272 : 256;
    float w = 0.f;
    if (klocal < 32 && k < K)
        w = (L == 0) ? W0[k * 256 + n] : Wmid[(L - 1) * 65536 + k * 256 + n];
    *(__half*)(g_wpack + (size_t)ch * WCH + n * 80 + klocal * 2) = __float2half_rn(w);
}

// ======================= PTX helpers =======================================
__device__ __forceinline__ uint32_t smem_u32(const void* p) {
    uint32_t a;
    asm("{ .reg .u64 t; cvta.to.shared.u64 t, %1; cvt.u32.u64 %0, t; }"
        : "=r"(a) : "l"(p));
    return a;
}
__device__ __forceinline__ void cp16b(char* dst, const char* src) {
    unsigned u = (unsigned)__cvta_generic_to_shared(dst);
    asm volatile("cp.async.cg.shared.global [%0], [%1], 16;" :: "r"(u), "l"(src));
}
__device__ __forceinline__ void cp_commit() { asm volatile("cp.async.commit_group;"); }
template<int N> __device__ __forceinline__ void cp_wait() {
    asm volatile("cp.async.wait_group %0;" :: "n"(N));
}
__device__ __forceinline__ void mbar_init(uint32_t a, uint32_t cnt) {
    asm volatile("mbarrier.init.shared.b64 [%0], %1;" :: "r"(a), "r"(cnt) : "memory");
}
__device__ __forceinline__ void mbar_expect_tx(uint32_t a, uint32_t bytes) {
    asm volatile("mbarrier.arrive.expect_tx.shared.b64 _, [%0], %1;"
                 :: "r"(a), "r"(bytes) : "memory");
}
__device__ __forceinline__ void bulk_g2s(uint32_t dst, const void* src,
                                         uint32_t bytes, uint32_t mbar) {
    asm volatile(
        "cp.async.bulk.shared::cluster.global.mbarrier::complete_tx::bytes "
        "[%0], [%1], %2, [%3];"
        :: "r"(dst), "l"(src), "r"(bytes), "r"(mbar) : "memory");
}
__device__ __forceinline__ void mbar_wait(uint32_t mbar, uint32_t parity) {
    asm volatile(
        "{\n\t.reg .pred P1;\n\t"
        "WAIT_LOOP_%=:\n\t"
        "mbarrier.try_wait.parity.acquire.cta.shared::cta.b64 P1, [%0], %1, 0x989680;\n\t"
        "@P1 bra.uni WAIT_DONE_%=;\n\t"
        "bra.uni WAIT_LOOP_%=;\n\t"
        "WAIT_DONE_%=:\n\t}"
        :: "r"(mbar), "r"(parity) : "memory");
}
__device__ __forceinline__ void ldm_x4(uint32_t* r, uint32_t addr) {
    asm volatile("ldmatrix.sync.aligned.m8n8.x4.shared.b16 {%0,%1,%2,%3}, [%4];"
                 : "=r"(r[0]), "=r"(r[1]), "=r"(r[2]), "=r"(r[3]) : "r"(addr));
}
__device__ __forceinline__ void mma16816(float* c, const uint32_t* a,
                                         uint32_t b0, uint32_t b1) {
    asm volatile(
        "mma.sync.aligned.m16n8k16.row.col.f32.f16.f16.f32 "
        "{%0,%1,%2,%3}, {%4,%5,%6,%7}, {%8,%9}, {%0,%1,%2,%3};"
        : "+f"(c[0]), "+f"(c[1]), "+f"(c[2]), "+f"(c[3])
        : "r"(a[0]), "r"(a[1]), "r"(a[2]), "r"(a[3]), "r"(b0), "r"(b1));
}
__device__ __forceinline__ uint32_t h2(float v0, float v1) {
    __half2 h = __floats2half2_rn(v0, v1);
    return *(uint32_t*)&h;
}
// full 64x64 MMA block: 32 HMMA
__device__ __forceinline__ void mma_block(float (*c)[8][4],
                                          const uint32_t (*a)[4],
                                          const uint32_t (*b)[4]) {
#pragma unroll
    for (int i = 0; i < 4; i++)
#pragma unroll
        for (int j = 0; j < 4; j++) {
            mma16816(c[i][2 * j],     a[i], b[j][0], b[j][1]);
            mma16816(c[i][2 * j + 1], a[i], b[j][2], b[j][3]);
        }
}

// ======================= node MLP (FFMA2 path, known good) =================
__device__ __forceinline__ unsigned long long pack2(float x) {
    unsigned long long r; unsigned v = __float_as_uint(x);
    asm("mov.b64 %0, {%1,%2};" : "=l"(r) : "r"(v), "r"(v));
    return r;
}
__device__ __forceinline__ void ffma2(unsigned long long& c, unsigned long long a,
                                      unsigned long long b) {
    asm("fma.rn.f32x2 %0, %1, %2, %0;" : "+l"(c) : "l"(a), "l"(b));
}
__device__ __forceinline__ float2 unpack2(unsigned long long v) {
    unsigned lo, hi;
    asm("mov.b64 {%0,%1}, %2;" : "=r"(lo), "=r"(hi) : "l"(v));
    float2 f; f.x = __uint_as_float(lo); f.y = __uint_as_float(hi);
    return f;
}
__device__ __forceinline__ void cp16f(float* dst, const float* src) {
    cp16b((char*)dst, (const char*)src);
}

constexpr int XSTR   = 260;
constexpr int A_SMEM = (TMN * XSTR + 2 * KCN * IN) * 4;

__global__ void __launch_bounds__(256, 2)
node_mlp_kernel(const float* __restrict__ x, const float* __restrict__ Wx,
                const float* __restrict__ bx)
{
    extern __shared__ float sm[];
    float* abuf = sm;
    float* bbuf = sm + TMN * XSTR;
    const int tid = threadIdx.x;
    const long long r0 = (long long)blockIdx.x * TMN;
    {
        int e = tid >> 2, q = tid & 3;
        const float* src = x + (r0 + e) * DN + q * 64;
        float* dst = abuf + e * XSTR + q * 64;
#pragma unroll
        for (int i = 0; i < 16; i++) cp16f(dst + i * 4, src + i * 4);
        cp_commit();
    }
    const int tr = tid >> 4, tc = tid & 15;
    const int m0 = tr * 4;
    unsigned long long acc[4][4];
#pragma unroll
    for (int i = 0; i < 4; i++)
#pragma unroll
        for (int j = 0; j < 4; j++) acc[i][j] = 0ull;
    constexpr int CHUNK = KCN * IN;
    {
#pragma unroll
        for (int i = 0; i < 2; i++)
            cp16f(bbuf + (tid + i * 256) * 4, Wx + (tid + i * 256) * 4);
        cp_commit();
    }
    const int nk = DN / KCN;
    for (int kc = 0; kc < nk; kc++) {
        if (kc + 1 < nk) {
            const float* src = Wx + (long long)(kc + 1) * CHUNK;
            float* dst = bbuf + ((kc + 1) & 1) * CHUNK;
#pragma unroll
            for (int i = 0; i < 2; i++)
                cp16f(dst + (tid + i * 256) * 4, src + (tid + i * 256) * 4);
            cp_commit();
            cp_wait<1>();
        } else cp_wait<0>();
        __syncthreads();
        const float* Bs = bbuf + (kc & 1) * CHUNK;
        const float* As = abuf + kc * KCN;
#pragma unroll
        for (int kk = 0; kk < KCN; kk++) {
            unsigned long long breg[4];
            const float* brow = Bs + kk * IN + 2 * tc;
#pragma unroll
            for (int j = 0; j < 4; j++)
                breg[j] = *(const unsigned long long*)(brow + 32 * j);
#pragma unroll
            for (int i = 0; i < 4; i++) {
                unsigned long long aa = pack2(As[(m0 + i) * XSTR + kk]);
#pragma unroll
                for (int j = 0; j < 4; j++) ffma2(acc[i][j], aa, breg[j]);
            }
        }
        __syncthreads();
    }
    float* gout = g_hnode + r0 * IN;
#pragma unroll
    for (int i = 0; i < 4; i++)
#pragma unroll
        for (int j = 0; j < 4; j++) {
            int n = 2 * tc + 32 * j;
            float2 v = unpack2(acc[i][j]);
            v.x += bx[n]; v.y += bx[n + 1];
            v.x = fmaxf(v.x, 0.01f * v.x);
            v.y = fmaxf(v.y, 0.01f * v.y);
            *(float2*)(gout + (long long)(m0 + i) * IN + n) = v;
        }
}

// ======================= edge MLP on fp16 mma.sync =========================
// SMEM layout (bytes):
constexpr int ASTRB  = 560;                      // A row stride: 280 fp16
constexpr int OFF_W  = 128 * ASTRB;              // 71680 (ring of 4 chunk bufs)
constexpr int OFF_PT = OFF_W;                    // classifier partials (reuse)
constexpr int OFF_MB = OFF_W + RING * WCH;       // 153600 (4 mbarriers)
constexpr int SMEM_E = OFF_MB + 64;

__global__ void __launch_bounds__(256, 1)
edge_hmma_kernel(const float* __restrict__ eattr,
                 const float* __restrict__ b0, const float* __restrict__ bmid,
                 const float* __restrict__ Wlast, const float* __restrict__ blast,
                 float* __restrict__ out, int E)
{
    extern __shared__ char smc[];
    const uint32_t sbase = smem_u32(smc);
    const int tid = threadIdx.x, wid = tid >> 5, lane = tid & 31;
    const int mg = wid >> 2, ng = wid & 3;        // 2 x 4 warp grid
    const int RB = 64 * mg, CB = 64 * ng;
    const long long e0 = (long long)blockIdx.x * 128;

    if (tid == 0)
        for (int i = 0; i < RING; i++) mbar_init(sbase + OFF_MB + i * 8, 1);
    __syncthreads();
    if (tid == 0) {
        for (int ci = 0; ci < RING; ci++) {
            uint32_t mb = sbase + OFF_MB + ci * 8;
            mbar_expect_tx(mb, WCH);
            bulk_g2s(sbase + OFF_W + ci * WCH, g_wpack + (size_t)ci * WCH, WCH, mb);
        }
    }

    // ---------------- gather ef -> A plane (fp16) ---------------------------
    {
        int e = tid >> 1, half = tid & 1;
        long long ge = e0 + e;
        int ridx = g_ei[ge];
        int cidx = g_ei[(long long)E + ge];
        const float4* hr4 = (const float4*)(g_hnode + (long long)ridx * IN);
        const float4* hc4 = (const float4*)(g_hnode + (long long)cidx * IN);
        const float4* ea4 = (const float4*)(eattr + ge * EA);
        int ch = half * 136;
#pragma unroll 2
        for (int g = 0; g < 34; g++) {
            int c = ch + 4 * g;
            float4 f = (c < 128) ? hr4[c >> 2]
                     : (c < 256) ? hc4[(c - 128) >> 2]
                                 : ea4[(c - 256) >> 2];
            char* pA = smc + e * ASTRB + c * 2;
            *(uint32_t*)(pA)     = h2(f.x, f.y);
            *(uint32_t*)(pA + 4) = h2(f.z, f.w);
        }
    }
    __syncthreads();

    // ---------------- per-thread invariant addresses ------------------------
    const int i7 = lane & 7;
    const int rowOff  = ((lane >> 3) & 1) * 8 + i7;
    const int aColOff = (lane >= 16) ? 16 : 0;            // bytes
    uint32_t aB[4];
#pragma unroll
    for (int i = 0; i < 4; i++)
        aB[i] = sbase + (uint32_t)(RB + 16 * i + rowOff) * ASTRB + aColOff;
    const int nIdx  = CB + ((lane >= 16) ? 8 : 0) + i7;
    const int bkOff = ((lane >> 3) & 1) * 16;             // bytes
    uint32_t bB[4];
#pragma unroll
    for (int j = 0; j < 4; j++) bB[j] = (uint32_t)(nIdx + 16 * j) * 80 + bkOff;

    float c[4][8][4];
#pragma unroll
    for (int i = 0; i < 4; i++)
#pragma unroll
        for (int j = 0; j < 8; j++)
#pragma unroll
            for (int q = 0; q < 4; q++) c[i][j][q] = 0.f;

    // ---------------- pipelined mainloop ------------------------------------
    uint32_t bf0[4][4], bf1[4][4];   // B fragments: s0 / s1 double buffer
    int chunkIdx = 0;

    // prologue: wait slot 0, preload B(chunk 0, s0)
    mbar_wait(sbase + OFF_MB + 0, 0);
#pragma unroll
    for (int j = 0; j < 4; j++) ldm_x4(bf0[j], sbase + OFF_W + bB[j]);

#pragma unroll 1
    for (int L = 0; L < 9; L++) {
        const int nch = (L == 0) ? 9 : 8;
#pragma unroll 1
        for (int cI = 0; cI < nch; cI++) {
            const int slot = chunkIdx & (RING - 1);
            const uint32_t wb = sbase + OFF_W + slot * WCH;
            const int kbB = cI * 64;                       // A byte offset
            const int nc = chunkIdx + 1;
            const bool hasNext = nc < NCHUNK;
            const uint32_t wbN = sbase + OFF_W + (nc & (RING - 1)) * WCH;
            uint32_t a[4][4];

            if (!(L == 0 && cI == 8)) {
                // load B(s1) then A(s0); MMA s0 overlaps these loads' drain
#pragma unroll
                for (int j = 0; j < 4; j++) ldm_x4(bf1[j], wb + bB[j] + 32);
#pragma unroll
                for (int i = 0; i < 4; i++) ldm_x4(a[i], aB[i] + kbB);
                mma_block(c, a, bf0);
                // prepare next chunk while s1 MMAs run
                if (hasNext)
                    mbar_wait(sbase + OFF_MB + (nc & (RING - 1)) * 8,
                              (uint32_t)((nc >> 2) & 1));
#pragma unroll
                for (int i = 0; i < 4; i++) ldm_x4(a[i], aB[i] + kbB + 32);
                if (hasNext) {
#pragma unroll
                    for (int j = 0; j < 4; j++) ldm_x4(bf0[j], wbN + bB[j]);
                }
                mma_block(c, a, bf1);
            } else {
                // single-step chunk (L0 tail, K=16)
#pragma unroll
                for (int i = 0; i < 4; i++) ldm_x4(a[i], aB[i] + kbB);
                mma_block(c, a, bf0);
                if (hasNext) {
                    mbar_wait(sbase + OFF_MB + (nc & (RING - 1)) * 8,
                              (uint32_t)((nc >> 2) & 1));
#pragma unroll
                    for (int j = 0; j < 4; j++) ldm_x4(bf0[j], wbN + bB[j]);
                }
            }

            __syncthreads();
            if (tid == 0 && chunkIdx + RING < NCHUNK) {
                const uint32_t mb2 = sbase + OFF_MB + slot * 8;
                mbar_expect_tx(mb2, WCH);
                bulk_g2s(sbase + OFF_W + slot * WCH,
                         g_wpack + (size_t)(chunkIdx + RING) * WCH, WCH, mb2);
            }
            chunkIdx++;
        }

        if (L < 8) {
            // epilogue: leaky(D + bias) -> fp16 -> A plane; zero C
            const float* bias = (L == 0) ? b0 : bmid + (L - 1) * 256;
#pragma unroll
            for (int i = 0; i < 4; i++) {
                const int row0 = RB + 16 * i + (lane >> 2);
#pragma unroll
                for (int j = 0; j < 8; j++) {
                    const int col = CB + 8 * j + 2 * (lane & 3);
                    float2 bb = __ldg((const float2*)(bias + col));
                    float v0 = c[i][j][0] + bb.x, v1 = c[i][j][1] + bb.y;
                    float v2 = c[i][j][2] + bb.x, v3 = c[i][j][3] + bb.y;
                    v0 = fmaxf(v0, 0.01f * v0); v1 = fmaxf(v1, 0.01f * v1);
                    v2 = fmaxf(v2, 0.01f * v2); v3 = fmaxf(v3, 0.01f * v3);
                    char* p0 = smc + row0 * ASTRB + col * 2;
                    *(uint32_t*)(p0)             = h2(v0, v1);
                    *(uint32_t*)(p0 + 8 * ASTRB) = h2(v2, v3);
                    c[i][j][0] = 0.f; c[i][j][1] = 0.f;
                    c[i][j][2] = 0.f; c[i][j][3] = 0.f;
                }
            }
            __syncthreads();
        }
    }

    // ---------------- classifier + log_softmax ------------------------------
    {
        const float* bias = bmid + 7 * 256;
        float p[4][2][3];
#pragma unroll
        for (int i = 0; i < 4; i++)
#pragma unroll
            for (int h = 0; h < 2; h++)
                p[i][h][0] = p[i][h][1] = p[i][h][2] = 0.f;
#pragma unroll
        for (int i = 0; i < 4; i++) {
#pragma unroll
            for (int j = 0; j < 8; j++) {
                const int col = CB + 8 * j + 2 * (lane & 3);
                float2 bb = __ldg((const float2*)(bias + col));
                float v0 = c[i][j][0] + bb.x, v1 = c[i][j][1] + bb.y;
                float v2 = c[i][j][2] + bb.x, v3 = c[i][j][3] + bb.y;
                v0 = fmaxf(v0, 0.01f * v0); v1 = fmaxf(v1, 0.01f * v1);
                v2 = fmaxf(v2, 0.01f * v2); v3 = fmaxf(v3, 0.01f * v3);
                const float* w0 = Wlast + col * 3;
#pragma unroll
                for (int k = 0; k < 3; k++) {
                    float wa = __ldg(w0 + k), wb2 = __ldg(w0 + 3 + k);
                    p[i][0][k] = fmaf(v0, wa, fmaf(v1, wb2, p[i][0][k]));
                    p[i][1][k] = fmaf(v2, wa, fmaf(v3, wb2, p[i][1][k]));
                }
            }
        }
#pragma unroll
        for (int i = 0; i < 4; i++)
#pragma unroll
            for (int h = 0; h < 2; h++)
#pragma unroll
                for (int k = 0; k < 3; k++) {
                    float v = p[i][h][k];
                    v += __shfl_xor_sync(0xffffffffu, v, 1);
                    v += __shfl_xor_sync(0xffffffffu, v, 2);
                    p[i][h][k] = v;
                }
        float* pt = (float*)(smc + OFF_PT);   // [128 rows][4 ng][3]
        if ((lane & 3) == 0) {
#pragma unroll
            for (int i = 0; i < 4; i++)
#pragma unroll
                for (int h = 0; h < 2; h++) {
                    int row = RB + 16 * i + (lane >> 2) + 8 * h;
#pragma unroll
                    for (int k = 0; k < 3; k++)
                        pt[(row * 4 + ng) * 3 + k] = p[i][h][k];
                }
        }
    }
    __syncthreads();
    if (tid < 128) {
        const float* pt = (const float*)(smc + OFF_PT);
        float l[3];
#pragma unroll
        for (int k = 0; k < 3; k++) {
            float s = __ldg(blast + k);
#pragma unroll
            for (int g = 0; g < 4; g++) s += pt[(tid * 4 + g) * 3 + k];
            l[k] = s;
        }
        float mx  = fmaxf(l[0], fmaxf(l[1], l[2]));
        float lse = mx + logf(expf(l[0] - mx) + expf(l[1] - mx) + expf(l[2] - mx));
        float* o = out + (e0 + tid) * NOUT;
        o[0] = l[0] - lse; o[1] = l[1] - lse; o[2] = l[2] - lse;
    }
}

// ===========================================================================
extern "C" void kernel_launch(void* const* d_in, const int* in_sizes, int n_in,
                              void* d_out, int out_size)
{
    const float* x      = (const float*)d_in[0];
    const int*   ei_raw = (const int*)d_in[1];
    const float* eattr  = (const float*)d_in[2];
    const float* Wx     = (const float*)d_in[3];
    const float* bx     = (const float*)d_in[4];
    const float* W0     = (const float*)d_in[5];
    const float* b0     = (const float*)d_in[6];
    const float* Wmid   = (const float*)d_in[7];
    const float* bmid   = (const float*)d_in[8];
    const float* Wlast  = (const float*)d_in[9];
    const float* blast  = (const float*)d_in[10];
    float* out = (float*)d_out;

    const int N  = in_sizes[0] / DN;
    const int E  = in_sizes[2] / EA;
    const int n2 = 2 * E;

    cudaFuncSetAttribute(node_mlp_kernel,
                         cudaFuncAttributeMaxDynamicSharedMemorySize, A_SMEM);
    cudaFuncSetAttribute(edge_hmma_kernel,
                         cudaFuncAttributeMaxDynamicSharedMemorySize, SMEM_E);

    detect_kernel<<<1, 256>>>(ei_raw);
    convert_kernel<<<(n2 + 255) / 256, 256>>>(ei_raw, n2);
    prep_pack<<<(NCHUNK * 256 * 40 + 255) / 256, 256>>>(W0, Wmid);
    node_mlp_kernel<<<N / TMN, 256, A_SMEM>>>(x, Wx, bx);
    edge_hmma_kernel<<<E / 128, 256, SMEM_E>>>(eattr, b0, bmid, Wlast, blast,
                                               out, E);
}

// round 9
// speedup vs baseline: 1.8721x; 1.1557x over previous
#include <cuda_runtime.h>
#include <cuda_fp16.h>
#include <cstdint>

// ---------------------------------------------------------------------------
// EdgeClassNet, fully fp16-HMMA. R9:
//  - node MLP on mma.sync fp16, writing fp16 g_hn directly (half the traffic)
//  - edge MLP pair-processes weight chunks (256 HMMA/SMSP between syncs)
// ---------------------------------------------------------------------------

constexpr int DN   = 256;   // node input dim
constexpr int IN   = 128;   // node hidden dim (halves per node in g_hn)
constexpr int EA   = 16;
constexpr int NOUT = 3;

constexpr int MAXN = 65536;
constexpr int MAXE = 262144;

// 73 weight chunks: layer0 = 9 chunks of K<=32, layers 1..8 = 8 chunks each.
// Each chunk image: [256 n][40 k] fp16 = 20480 B.
constexpr int NCHUNK = 73;
constexpr int WCH    = 20480;
constexpr int RING   = 4;

__device__ __half g_hn[MAXN * IN];                     // 16 MB fp16 node hidden
__device__ int    g_ei[2 * MAXE];
__device__ int    g_is64;
__device__ __align__(16) unsigned char g_wpack[NCHUNK * WCH];
__device__ __align__(16) __half g_wxpack[128 * 264];   // node W: [n][k pad]

// ======================= small utility kernels =============================
__global__ void detect_kernel(const int* __restrict__ ei_raw) {
    __shared__ int cnt;
    if (threadIdx.x == 0) cnt = 0;
    __syncthreads();
    if (ei_raw[2 * threadIdx.x + 1] != 0) atomicAdd(&cnt, 1);
    __syncthreads();
    if (threadIdx.x == 0) g_is64 = (cnt == 0) ? 1 : 0;
}
__global__ void convert_kernel(const int* __restrict__ ei_raw, int n2e) {
    int i = blockIdx.x * blockDim.x + threadIdx.x;
    if (i >= n2e) return;
    g_ei[i] = g_is64 ? ei_raw[2 * i] : ei_raw[i];
}
// pack edge weights into per-chunk SMEM images ([n][k], fp16)
__global__ void prep_pack(const float* __restrict__ W0,
                          const float* __restrict__ Wmid) {
    int idx = blockIdx.x * 256 + threadIdx.x;       // over 73*256*40
    if (idx >= NCHUNK * 256 * 40) return;
    int klocal = idx % 40;
    int n  = (idx / 40) & 255;
    int ch = idx / (40 * 256);
    int L, cc;
    if (ch < 9) { L = 0; cc = ch; } else { L = 1 + (ch - 9) / 8; cc = (ch - 9) & 7; }
    int k = cc * 32 + klocal;
    int K = (L == 0) ? 272 : 256;
    float w = 0.f;
    if (klocal < 32 && k < K)
        w = (L == 0) ? W0[k * 256 + n] : Wmid[(L - 1) * 65536 + k * 256 + n];
    *(__half*)(g_wpack + (size_t)ch * WCH + n * 80 + klocal * 2) = __float2half_rn(w);
}
// pack node W: Wx [256 k][128 n] -> [128 n][264 k] fp16
__global__ void prep_wx(const float* __restrict__ Wx) {
    int idx = blockIdx.x * 256 + threadIdx.x;       // over 128*264
    if (idx >= 128 * 264) return;
    int n = idx / 264, k = idx % 264;
    g_wxpack[idx] = __float2half_rn(k < 256 ? Wx[k * 128 + n] : 0.f);
}

// ======================= PTX helpers =======================================
__device__ __forceinline__ uint32_t smem_u32(const void* p) {
    uint32_t a;
    asm("{ .reg .u64 t; cvta.to.shared.u64 t, %1; cvt.u32.u64 %0, t; }"
        : "=r"(a) : "l"(p));
    return a;
}
__device__ __forceinline__ void cp16b(char* dst, const char* src) {
    unsigned u = (unsigned)__cvta_generic_to_shared(dst);
    asm volatile("cp.async.cg.shared.global [%0], [%1], 16;" :: "r"(u), "l"(src));
}
__device__ __forceinline__ void cp_commit() { asm volatile("cp.async.commit_group;"); }
template<int N> __device__ __forceinline__ void cp_wait() {
    asm volatile("cp.async.wait_group %0;" :: "n"(N));
}
__device__ __forceinline__ void mbar_init(uint32_t a, uint32_t cnt) {
    asm volatile("mbarrier.init.shared.b64 [%0], %1;" :: "r"(a), "r"(cnt) : "memory");
}
__device__ __forceinline__ void mbar_expect_tx(uint32_t a, uint32_t bytes) {
    asm volatile("mbarrier.arrive.expect_tx.shared.b64 _, [%0], %1;"
                 :: "r"(a), "r"(bytes) : "memory");
}
__device__ __forceinline__ void bulk_g2s(uint32_t dst, const void* src,
                                         uint32_t bytes, uint32_t mbar) {
    asm volatile(
        "cp.async.bulk.shared::cluster.global.mbarrier::complete_tx::bytes "
        "[%0], [%1], %2, [%3];"
        :: "r"(dst), "l"(src), "r"(bytes), "r"(mbar) : "memory");
}
__device__ __forceinline__ void mbar_wait(uint32_t mbar, uint32_t parity) {
    asm volatile(
        "{\n\t.reg .pred P1;\n\t"
        "WAIT_LOOP_%=:\n\t"
        "mbarrier.try_wait.parity.acquire.cta.shared::cta.b64 P1, [%0], %1, 0x989680;\n\t"
        "@P1 bra.uni WAIT_DONE_%=;\n\t"
        "bra.uni WAIT_LOOP_%=;\n\t"
        "WAIT_DONE_%=:\n\t}"
        :: "r"(mbar), "r"(parity) : "memory");
}
__device__ __forceinline__ void ldm_x4(uint32_t* r, uint32_t addr) {
    asm volatile("ldmatrix.sync.aligned.m8n8.x4.shared.b16 {%0,%1,%2,%3}, [%4];"
                 : "=r"(r[0]), "=r"(r[1]), "=r"(r[2]), "=r"(r[3]) : "r"(addr));
}
__device__ __forceinline__ void mma16816(float* c, const uint32_t* a,
                                         uint32_t b0, uint32_t b1) {
    asm volatile(
        "mma.sync.aligned.m16n8k16.row.col.f32.f16.f16.f32 "
        "{%0,%1,%2,%3}, {%4,%5,%6,%7}, {%8,%9}, {%0,%1,%2,%3};"
        : "+f"(c[0]), "+f"(c[1]), "+f"(c[2]), "+f"(c[3])
        : "r"(a[0]), "r"(a[1]), "r"(a[2]), "r"(a[3]), "r"(b0), "r"(b1));
}
__device__ __forceinline__ uint32_t h2(float v0, float v1) {
    __half2 h = __floats2half2_rn(v0, v1);
    return *(uint32_t*)&h;
}
// full 64x64 MMA block: 32 HMMA
__device__ __forceinline__ void mma_block(float (*c)[8][4],
                                          const uint32_t (*a)[4],
                                          const uint32_t (*b)[4]) {
#pragma unroll
    for (int i = 0; i < 4; i++)
#pragma unroll
        for (int j = 0; j < 4; j++) {
            mma16816(c[i][2 * j],     a[i], b[j][0], b[j][1]);
            mma16816(c[i][2 * j + 1], a[i], b[j][2], b[j][3]);
        }
}

// ======================= node MLP on fp16 HMMA =============================
// 128 threads, 64 rows/CTA; A [64][280] halves, W [128][264] halves in SMEM.
constexpr int NA_STR  = 280;                     // halves
constexpr int NW_STR  = 264;                     // halves
constexpr int NOFF_W  = 64 * NA_STR * 2;         // 35840 B
constexpr int SMEM_N  = NOFF_W + 128 * NW_STR * 2;  // 103424 B

__global__ void __launch_bounds__(128, 2)
node_hmma_kernel(const float* __restrict__ x, const float* __restrict__ bx)
{
    extern __shared__ char smc[];
    const uint32_t sbase = smem_u32(smc);
    const int tid = threadIdx.x, wid = tid >> 5, lane = tid & 31;
    const long long r0 = (long long)blockIdx.x * 64;

    // stage W (one shot, straight copy of packed image)
    {
        const char* src = (const char*)g_wxpack;
        char* dst = smc + NOFF_W;
#pragma unroll
        for (int i = 0; i < 33; i++) {
            int idx = tid + i * 128;
            cp16b(dst + idx * 16, src + idx * 16);
        }
        cp_commit();
    }
    // stage x tile, converting fp32 -> fp16
    {
        int row = tid >> 1, q = tid & 1;
        const float4* x4 = (const float4*)(x + (r0 + row) * DN) + q * 32;
        char* dst = smc + row * (NA_STR * 2) + q * 256;
#pragma unroll
        for (int g = 0; g < 32; g++) {
            float4 f = x4[g];
            *(uint32_t*)(dst + 8 * g)     = h2(f.x, f.y);
            *(uint32_t*)(dst + 8 * g + 4) = h2(f.z, f.w);
        }
    }
    cp_wait<0>();
    __syncthreads();

    const int i7 = lane & 7;
    const int rowOff  = ((lane >> 3) & 1) * 8 + i7;
    const int aColOff = (lane >= 16) ? 16 : 0;
    const uint32_t aBase = sbase + (uint32_t)(16 * wid + rowOff) * (NA_STR * 2) + aColOff;
    const int nIdx  = ((lane >= 16) ? 8 : 0) + i7;
    const int bkOff = ((lane >> 3) & 1) * 16;
    uint32_t bB[8];
#pragma unroll
    for (int j = 0; j < 8; j++)
        bB[j] = sbase + NOFF_W + (uint32_t)(nIdx + 16 * j) * (NW_STR * 2) + bkOff;

    float c[16][4];
#pragma unroll
    for (int j = 0; j < 16; j++)
#pragma unroll
        for (int q = 0; q < 4; q++) c[j][q] = 0.f;

#pragma unroll 4
    for (int k = 0; k < 16; k++) {
        uint32_t a[4];
        ldm_x4(a, aBase + k * 32);
#pragma unroll
        for (int j = 0; j < 8; j++) {
            uint32_t b[4];
            ldm_x4(b, bB[j] + k * 32);
            mma16816(c[2 * j],     a, b[0], b[1]);
            mma16816(c[2 * j + 1], a, b[2], b[3]);
        }
    }

    // epilogue: bias + leaky -> fp16 g_hn
    const long long rb = r0 + 16 * wid + (lane >> 2);
#pragma unroll
    for (int j = 0; j < 16; j++) {
        int col = 8 * j + 2 * (lane & 3);
        float2 bb = __ldg((const float2*)(bx + col));
#pragma unroll
        for (int r8 = 0; r8 < 2; r8++) {
            float v0 = c[j][2 * r8]     + bb.x;
            float v1 = c[j][2 * r8 + 1] + bb.y;
            v0 = fmaxf(v0, 0.01f * v0);
            v1 = fmaxf(v1, 0.01f * v1);
            *(uint32_t*)((char*)g_hn + ((rb + 8 * r8) * IN + col) * 2) = h2(v0, v1);
        }
    }
}

// ======================= edge MLP on fp16 mma.sync =========================
constexpr int ASTRB  = 560;                      // A row stride: 280 fp16
constexpr int OFF_W  = 128 * ASTRB;              // 71680 (ring of 4 chunk bufs)
constexpr int OFF_PT = OFF_W;                    // classifier partials (reuse)
constexpr int OFF_MB = OFF_W + RING * WCH;       // 153600 (4 mbarriers)
constexpr int SMEM_E = OFF_MB + 64;

__global__ void __launch_bounds__(256, 1)
edge_hmma_kernel(const float* __restrict__ eattr,
                 const float* __restrict__ b0, const float* __restrict__ bmid,
                 const float* __restrict__ Wlast, const float* __restrict__ blast,
                 float* __restrict__ out, int E)
{
    extern __shared__ char smc[];
    const uint32_t sbase = smem_u32(smc);
    const int tid = threadIdx.x, wid = tid >> 5, lane = tid & 31;
    const int mg = wid >> 2, ng = wid & 3;        // 2 x 4 warp grid
    const int RB = 64 * mg, CB = 64 * ng;
    const long long e0 = (long long)blockIdx.x * 128;

    if (tid == 0)
        for (int i = 0; i < RING; i++) mbar_init(sbase + OFF_MB + i * 8, 1);
    __syncthreads();
    if (tid == 0) {
        for (int ci = 0; ci < RING; ci++) {
            uint32_t mb = sbase + OFF_MB + ci * 8;
            mbar_expect_tx(mb, WCH);
            bulk_g2s(sbase + OFF_W + ci * WCH, g_wpack + (size_t)ci * WCH, WCH, mb);
        }
    }

    // ---------------- gather ef -> A plane (fp16 copies) --------------------
    {
        int e = tid >> 1, half = tid & 1;
        long long ge = e0 + e;
        const uint4* hr4 = (const uint4*)(g_hn + (size_t)g_ei[ge] * IN);
        const uint4* hc4 = (const uint4*)(g_hn + (size_t)g_ei[(long long)E + ge] * IN);
        const float4* ea4 = (const float4*)(eattr + ge * EA);
        uint4* dst = (uint4*)(smc + e * ASTRB + half * 272);
        if (half == 0) {
#pragma unroll
            for (int g = 0; g < 16; g++) dst[g] = hr4[g];
            dst[16] = hc4[0];
        } else {
#pragma unroll
            for (int g = 0; g < 15; g++) dst[g] = hc4[1 + g];
#pragma unroll
            for (int g = 0; g < 2; g++) {
                float4 f0 = ea4[2 * g], f1 = ea4[2 * g + 1];
                uint4 u;
                u.x = h2(f0.x, f0.y); u.y = h2(f0.z, f0.w);
                u.z = h2(f1.x, f1.y); u.w = h2(f1.z, f1.w);
                dst[15 + g] = u;
            }
        }
    }
    __syncthreads();

    // ---------------- per-thread invariant addresses ------------------------
    const int i7 = lane & 7;
    const int rowOff  = ((lane >> 3) & 1) * 8 + i7;
    const int aColOff = (lane >= 16) ? 16 : 0;            // bytes
    uint32_t aB[4];
#pragma unroll
    for (int i = 0; i < 4; i++)
        aB[i] = sbase + (uint32_t)(RB + 16 * i + rowOff) * ASTRB + aColOff;
    const int nIdx  = CB + ((lane >= 16) ? 8 : 0) + i7;
    const int bkOff = ((lane >> 3) & 1) * 16;             // bytes
    uint32_t bB[4];
#pragma unroll
    for (int j = 0; j < 4; j++) bB[j] = (uint32_t)(nIdx + 16 * j) * 80 + bkOff;

    float c[4][8][4];
#pragma unroll
    for (int i = 0; i < 4; i++)
#pragma unroll
        for (int j = 0; j < 8; j++)
#pragma unroll
            for (int q = 0; q < 4; q++) c[i][j][q] = 0.f;

    // ---------------- pair-pipelined mainloop -------------------------------
    uint32_t bf0[4][4], bf1[4][4];
    int chunkIdx = 0;

    // prologue: wait slot 0, preload B(chunk 0, s0)
    mbar_wait(sbase + OFF_MB + 0, 0);
#pragma unroll
    for (int j = 0; j < 4; j++) ldm_x4(bf0[j], sbase + OFF_W + bB[j]);

#pragma unroll 1
    for (int L = 0; L < 9; L++) {
#pragma unroll 1
        for (int p = 0; p < 4; p++) {
            const int ca = chunkIdx, cb = chunkIdx + 1;
            const uint32_t wa = sbase + OFF_W + (ca & 3) * WCH;
            const int kA = p * 128, kB = p * 128 + 64;
            uint32_t a[4][4];

            // chunk ca
#pragma unroll
            for (int j = 0; j < 4; j++) ldm_x4(bf1[j], wa + bB[j] + 32);
#pragma unroll
            for (int i = 0; i < 4; i++) ldm_x4(a[i], aB[i] + kA);
            mma_block(c, a, bf0);
            mbar_wait(sbase + OFF_MB + (cb & 3) * 8, (uint32_t)((cb >> 2) & 1));
            const uint32_t wbuf = sbase + OFF_W + (cb & 3) * WCH;
#pragma unroll
            for (int i = 0; i < 4; i++) ldm_x4(a[i], aB[i] + kA + 32);
#pragma unroll
            for (int j = 0; j < 4; j++) ldm_x4(bf0[j], wbuf + bB[j]);
            mma_block(c, a, bf1);
            // chunk cb
#pragma unroll
            for (int j = 0; j < 4; j++) ldm_x4(bf1[j], wbuf + bB[j] + 32);
#pragma unroll
            for (int i = 0; i < 4; i++) ldm_x4(a[i], aB[i] + kB);
            mma_block(c, a, bf0);
            const int nc = chunkIdx + 2;
            const bool hn = nc < NCHUNK;
            if (hn) mbar_wait(sbase + OFF_MB + (nc & 3) * 8,
                              (uint32_t)((nc >> 2) & 1));
#pragma unroll
            for (int i = 0; i < 4; i++) ldm_x4(a[i], aB[i] + kB + 32);
            if (hn) {
                const uint32_t wn = sbase + OFF_W + (nc & 3) * WCH;
#pragma unroll
                for (int j = 0; j < 4; j++) ldm_x4(bf0[j], wn + bB[j]);
            }
            mma_block(c, a, bf1);

            __syncthreads();
            if (tid == 0) {
                if (ca + RING < NCHUNK) {
                    const uint32_t mb2 = sbase + OFF_MB + (ca & 3) * 8;
                    mbar_expect_tx(mb2, WCH);
                    bulk_g2s(sbase + OFF_W + (ca & 3) * WCH,
                             g_wpack + (size_t)(ca + RING) * WCH, WCH, mb2);
                }
                if (cb + RING < NCHUNK) {
                    const uint32_t mb2 = sbase + OFF_MB + (cb & 3) * 8;
                    mbar_expect_tx(mb2, WCH);
                    bulk_g2s(sbase + OFF_W + (cb & 3) * WCH,
                             g_wpack + (size_t)(cb + RING) * WCH, WCH, mb2);
                }
            }
            chunkIdx += 2;
        }

        if (L == 0) {
            // tail chunk 8 of layer 0 (single k16 step); bf0 = B(8, s0)
            uint32_t a[4][4];
#pragma unroll
            for (int i = 0; i < 4; i++) ldm_x4(a[i], aB[i] + 512);
            mma_block(c, a, bf0);
            const int nc = 9;
            mbar_wait(sbase + OFF_MB + (nc & 3) * 8, (uint32_t)((nc >> 2) & 1));
            const uint32_t wn = sbase + OFF_W + (nc & 3) * WCH;
#pragma unroll
            for (int j = 0; j < 4; j++) ldm_x4(bf0[j], wn + bB[j]);
            __syncthreads();
            if (tid == 0 && 8 + RING < NCHUNK) {
                const uint32_t mb2 = sbase + OFF_MB + (8 & 3) * 8;
                mbar_expect_tx(mb2, WCH);
                bulk_g2s(sbase + OFF_W + (8 & 3) * WCH,
                         g_wpack + (size_t)(8 + RING) * WCH, WCH, mb2);
            }
            chunkIdx = 9;
        }

        if (L < 8) {
            // epilogue: leaky(D + bias) -> fp16 -> A plane; zero C
            const float* bias = (L == 0) ? b0 : bmid + (L - 1) * 256;
#pragma unroll
            for (int i = 0; i < 4; i++) {
                const int row0 = RB + 16 * i + (lane >> 2);
#pragma unroll
                for (int j = 0; j < 8; j++) {
                    const int col = CB + 8 * j + 2 * (lane & 3);
                    float2 bb = __ldg((const float2*)(bias + col));
                    float v0 = c[i][j][0] + bb.x, v1 = c[i][j][1] + bb.y;
                    float v2 = c[i][j][2] + bb.x, v3 = c[i][j][3] + bb.y;
                    v0 = fmaxf(v0, 0.01f * v0); v1 = fmaxf(v1, 0.01f * v1);
                    v2 = fmaxf(v2, 0.01f * v2); v3 = fmaxf(v3, 0.01f * v3);
                    char* p0 = smc + row0 * ASTRB + col * 2;
                    *(uint32_t*)(p0)             = h2(v0, v1);
                    *(uint32_t*)(p0 + 8 * ASTRB) = h2(v2, v3);
                    c[i][j][0] = 0.f; c[i][j][1] = 0.f;
                    c[i][j][2] = 0.f; c[i][j][3] = 0.f;
                }
            }
            __syncthreads();
        }
    }

    // ---------------- classifier + log_softmax ------------------------------
    {
        const float* bias = bmid + 7 * 256;
        float p[4][2][3];
#pragma unroll
        for (int i = 0; i < 4; i++)
#pragma unroll
            for (int h = 0; h < 2; h++)
                p[i][h][0] = p[i][h][1] = p[i][h][2] = 0.f;
#pragma unroll
        for (int i = 0; i < 4; i++) {
#pragma unroll
            for (int j = 0; j < 8; j++) {
                const int col = CB + 8 * j + 2 * (lane & 3);
                float2 bb = __ldg((const float2*)(bias + col));
                float v0 = c[i][j][0] + bb.x, v1 = c[i][j][1] + bb.y;
                float v2 = c[i][j][2] + bb.x, v3 = c[i][j][3] + bb.y;
                v0 = fmaxf(v0, 0.01f * v0); v1 = fmaxf(v1, 0.01f * v1);
                v2 = fmaxf(v2, 0.01f * v2); v3 = fmaxf(v3, 0.01f * v3);
                const float* w0 = Wlast + col * 3;
#pragma unroll
                for (int k = 0; k < 3; k++) {
                    float wa = __ldg(w0 + k), wb2 = __ldg(w0 + 3 + k);
                    p[i][0][k] = fmaf(v0, wa, fmaf(v1, wb2, p[i][0][k]));
                    p[i][1][k] = fmaf(v2, wa, fmaf(v3, wb2, p[i][1][k]));
                }
            }
        }
#pragma unroll
        for (int i = 0; i < 4; i++)
#pragma unroll
            for (int h = 0; h < 2; h++)
#pragma unroll
                for (int k = 0; k < 3; k++) {
                    float v = p[i][h][k];
                    v += __shfl_xor_sync(0xffffffffu, v, 1);
                    v += __shfl_xor_sync(0xffffffffu, v, 2);
                    p[i][h][k] = v;
                }
        float* pt = (float*)(smc + OFF_PT);   // [128 rows][4 ng][3]
        if ((lane & 3) == 0) {
#pragma unroll
            for (int i = 0; i < 4; i++)
#pragma unroll
                for (int h = 0; h < 2; h++) {
                    int row = RB + 16 * i + (lane >> 2) + 8 * h;
#pragma unroll
                    for (int k = 0; k < 3; k++)
                        pt[(row * 4 + ng) * 3 + k] = p[i][h][k];
                }
        }
    }
    __syncthreads();
    if (tid < 128) {
        const float* pt = (const float*)(smc + OFF_PT);
        float l[3];
#pragma unroll
        for (int k = 0; k < 3; k++) {
            float s = __ldg(blast + k);
#pragma unroll
            for (int g = 0; g < 4; g++) s += pt[(tid * 4 + g) * 3 + k];
            l[k] = s;
        }
        float mx  = fmaxf(l[0], fmaxf(l[1], l[2]));
        float lse = mx + logf(expf(l[0] - mx) + expf(l[1] - mx) + expf(l[2] - mx));
        float* o = out + (e0 + tid) * NOUT;
        o[0] = l[0] - lse; o[1] = l[1] - lse; o[2] = l[2] - lse;
    }
}

// ===========================================================================
extern "C" void kernel_launch(void* const* d_in, const int* in_sizes, int n_in,
                              void* d_out, int out_size)
{
    const float* x      = (const float*)d_in[0];
    const int*   ei_raw = (const int*)d_in[1];
    const float* eattr  = (const float*)d_in[2];
    const float* Wx     = (const float*)d_in[3];
    const float* bx     = (const float*)d_in[4];
    const float* W0     = (const float*)d_in[5];
    const float* b0     = (const float*)d_in[6];
    const float* Wmid   = (const float*)d_in[7];
    const float* bmid   = (const float*)d_in[8];
    const float* Wlast  = (const float*)d_in[9];
    const float* blast  = (const float*)d_in[10];
    float* out = (float*)d_out;

    const int N  = in_sizes[0] / DN;
    const int E  = in_sizes[2] / EA;
    const int n2 = 2 * E;

    cudaFuncSetAttribute(node_hmma_kernel,
                         cudaFuncAttributeMaxDynamicSharedMemorySize, SMEM_N);
    cudaFuncSetAttribute(edge_hmma_kernel,
                         cudaFuncAttributeMaxDynamicSharedMemorySize, SMEM_E);

    detect_kernel<<<1, 256>>>(ei_raw);
    convert_kernel<<<(n2 + 255) / 256, 256>>>(ei_raw, n2);
    prep_pack<<<(NCHUNK * 256 * 40 + 255) / 256, 256>>>(W0, Wmid);
    prep_wx<<<(128 * 264 + 255) / 256, 256>>>(Wx);
    node_hmma_kernel<<<N / 64, 128, SMEM_N>>>(x, bx);
    edge_hmma_kernel<<<E / 128, 256, SMEM_E>>>(eattr, b0, bmid, Wlast, blast,
                                               out, E);
}

// round 10
// speedup vs baseline: 1.9864x; 1.0611x over previous
#include <cuda_runtime.h>
#include <cuda_fp16.h>
#include <cstdint>

// ---------------------------------------------------------------------------
// EdgeClassNet, fully fp16-HMMA. R10:
//  - edge: paired weight fetches (40KB bulk, 3-slot ring) -> 1 mbar_wait / 2 chunks
//  - single merged prep kernel (convert + pack + wx)
//  - node: coalesced x staging
// ---------------------------------------------------------------------------

constexpr int DN   = 256;   // node input dim
constexpr int IN   = 128;   // node hidden dim
constexpr int EA   = 16;
constexpr int NOUT = 3;

constexpr int MAXN = 65536;
constexpr int MAXE = 262144;

// 73 weight chunks: layer0 = 9 chunks of K<=32, layers 1..8 = 8 chunks each.
// Each chunk image: [256 n][40 k] fp16 = 20480 B. Fetched in PAIRS of 2.
constexpr int NCHUNK = 73;
constexpr int WCH    = 20480;

__device__ __half g_hn[MAXN * IN];
__device__ int    g_ei[2 * MAXE];
__device__ __align__(16) unsigned char g_wpack[NCHUNK * WCH];
__device__ __align__(16) __half g_wxpack[128 * 264];   // node W: [n][k pad]

// ======================= merged prep kernel ================================
constexpr int NPACK_BLK = (NCHUNK * 256 * 40) / 256;   // 2920
constexpr int NWX_BLK   = (128 * 264) / 256;           // 132

__global__ void prep_all(const int* __restrict__ ei_raw,
                         const float* __restrict__ W0,
                         const float* __restrict__ Wmid,
                         const float* __restrict__ Wx, int n2e)
{
    const int nconv = (n2e + 255) >> 8;
    const int b = blockIdx.x;
    if (b < nconv) {
        // dtype-detect (first 256 odd words, cached) + convert
        int nz = __syncthreads_or(ei_raw[2 * threadIdx.x + 1] != 0);
        int i = b * 256 + threadIdx.x;
        if (i < n2e) g_ei[i] = nz ? ei_raw[i] : ei_raw[2 * i];
    } else if (b < nconv + NPACK_BLK) {
        int idx = (b - nconv) * 256 + threadIdx.x;     // over 73*256*40
        int klocal = idx % 40;
        int n  = (idx / 40) & 255;
        int ch = idx / (40 * 256);
        int L, cc;
        if (ch < 9) { L = 0; cc = ch; } else { L = 1 + (ch - 9) / 8; cc = (ch - 9) & 7; }
        int k = cc * 32 + klocal;
        int K = (L == 0) ? 272 : 256;
        float w = 0.f;
        if (klocal < 32 && k < K)
            w = (L == 0) ? W0[k * 256 + n] : Wmid[(L - 1) * 65536 + k * 256 + n];
        *(__half*)(g_wpack + (size_t)ch * WCH + n * 80 + klocal * 2) = __float2half_rn(w);
    } else {
        int idx = (b - nconv - NPACK_BLK) * 256 + threadIdx.x;  // over 128*264
        int n = idx / 264, k = idx % 264;
        g_wxpack[idx] = __float2half_rn(k < 256 ? Wx[k * 128 + n] : 0.f);
    }
}

// ======================= PTX helpers =======================================
__device__ __forceinline__ uint32_t smem_u32(const void* p) {
    uint32_t a;
    asm("{ .reg .u64 t; cvta.to.shared.u64 t, %1; cvt.u32.u64 %0, t; }"
        : "=r"(a) : "l"(p));
    return a;
}
__device__ __forceinline__ void cp16b(char* dst, const char* src) {
    unsigned u = (unsigned)__cvta_generic_to_shared(dst);
    asm volatile("cp.async.cg.shared.global [%0], [%1], 16;" :: "r"(u), "l"(src));
}
__device__ __forceinline__ void cp_commit() { asm volatile("cp.async.commit_group;"); }
template<int N> __device__ __forceinline__ void cp_wait() {
    asm volatile("cp.async.wait_group %0;" :: "n"(N));
}
__device__ __forceinline__ void mbar_init(uint32_t a, uint32_t cnt) {
    asm volatile("mbarrier.init.shared.b64 [%0], %1;" :: "r"(a), "r"(cnt) : "memory");
}
__device__ __forceinline__ void mbar_expect_tx(uint32_t a, uint32_t bytes) {
    asm volatile("mbarrier.arrive.expect_tx.shared.b64 _, [%0], %1;"
                 :: "r"(a), "r"(bytes) : "memory");
}
__device__ __forceinline__ void bulk_g2s(uint32_t dst, const void* src,
                                         uint32_t bytes, uint32_t mbar) {
    asm volatile(
        "cp.async.bulk.shared::cluster.global.mbarrier::complete_tx::bytes "
        "[%0], [%1], %2, [%3];"
        :: "r"(dst), "l"(src), "r"(bytes), "r"(mbar) : "memory");
}
__device__ __forceinline__ void mbar_wait(uint32_t mbar, uint32_t parity) {
    asm volatile(
        "{\n\t.reg .pred P1;\n\t"
        "WAIT_LOOP_%=:\n\t"
        "mbarrier.try_wait.parity.acquire.cta.shared::cta.b64 P1, [%0], %1, 0x989680;\n\t"
        "@P1 bra.uni WAIT_DONE_%=;\n\t"
        "bra.uni WAIT_LOOP_%=;\n\t"
        "WAIT_DONE_%=:\n\t}"
        :: "r"(mbar), "r"(parity) : "memory");
}
__device__ __forceinline__ void ldm_x4(uint32_t* r, uint32_t addr) {
    asm volatile("ldmatrix.sync.aligned.m8n8.x4.shared.b16 {%0,%1,%2,%3}, [%4];"
                 : "=r"(r[0]), "=r"(r[1]), "=r"(r[2]), "=r"(r[3]) : "r"(addr));
}
__device__ __forceinline__ void mma16816(float* c, const uint32_t* a,
                                         uint32_t b0, uint32_t b1) {
    asm volatile(
        "mma.sync.aligned.m16n8k16.row.col.f32.f16.f16.f32 "
        "{%0,%1,%2,%3}, {%4,%5,%6,%7}, {%8,%9}, {%0,%1,%2,%3};"
        : "+f"(c[0]), "+f"(c[1]), "+f"(c[2]), "+f"(c[3])
        : "r"(a[0]), "r"(a[1]), "r"(a[2]), "r"(a[3]), "r"(b0), "r"(b1));
}
__device__ __forceinline__ uint32_t h2(float v0, float v1) {
    __half2 h = __floats2half2_rn(v0, v1);
    return *(uint32_t*)&h;
}
// full 64x64 MMA block: 32 HMMA
__device__ __forceinline__ void mma_block(float (*c)[8][4],
                                          const uint32_t (*a)[4],
                                          const uint32_t (*b)[4]) {
#pragma unroll
    for (int i = 0; i < 4; i++)
#pragma unroll
        for (int j = 0; j < 4; j++) {
            mma16816(c[i][2 * j],     a[i], b[j][0], b[j][1]);
            mma16816(c[i][2 * j + 1], a[i], b[j][2], b[j][3]);
        }
}

// ======================= node MLP on fp16 HMMA =============================
constexpr int NA_STR  = 280;                     // halves
constexpr int NW_STR  = 264;                     // halves
constexpr int NOFF_W  = 64 * NA_STR * 2;         // 35840 B
constexpr int SMEM_N  = NOFF_W + 128 * NW_STR * 2;  // 103424 B

__global__ void __launch_bounds__(128, 2)
node_hmma_kernel(const float* __restrict__ x, const float* __restrict__ bx)
{
    extern __shared__ char smc[];
    const uint32_t sbase = smem_u32(smc);
    const int tid = threadIdx.x, wid = tid >> 5, lane = tid & 31;
    const long long r0 = (long long)blockIdx.x * 64;

    // stage W (one shot, straight copy of packed image)
    {
        const char* src = (const char*)g_wxpack;
        char* dst = smc + NOFF_W;
#pragma unroll
        for (int i = 0; i < 33; i++) {
            int idx = tid + i * 128;
            cp16b(dst + idx * 16, src + idx * 16);
        }
        cp_commit();
    }
    // stage x tile, fp32 -> fp16, fully coalesced (thread i loads float4 i+128g)
    {
        const float4* x4 = (const float4*)(x + r0 * DN);
#pragma unroll
        for (int g = 0; g < 32; g++) {
            int f = tid + 128 * g;
            int row = f >> 6, col = f & 63;
            float4 v = x4[f];
            char* dst = smc + row * (NA_STR * 2) + col * 8;
            *(uint32_t*)(dst)     = h2(v.x, v.y);
            *(uint32_t*)(dst + 4) = h2(v.z, v.w);
        }
    }
    cp_wait<0>();
    __syncthreads();

    const int i7 = lane & 7;
    const int rowOff  = ((lane >> 3) & 1) * 8 + i7;
    const int aColOff = (lane >= 16) ? 16 : 0;
    const uint32_t aBase = sbase + (uint32_t)(16 * wid + rowOff) * (NA_STR * 2) + aColOff;
    const int nIdx  = ((lane >= 16) ? 8 : 0) + i7;
    const int bkOff = ((lane >> 3) & 1) * 16;
    uint32_t bB[8];
#pragma unroll
    for (int j = 0; j < 8; j++)
        bB[j] = sbase + NOFF_W + (uint32_t)(nIdx + 16 * j) * (NW_STR * 2) + bkOff;

    float c[16][4];
#pragma unroll
    for (int j = 0; j < 16; j++)
#pragma unroll
        for (int q = 0; q < 4; q++) c[j][q] = 0.f;

#pragma unroll 4
    for (int k = 0; k < 16; k++) {
        uint32_t a[4];
        ldm_x4(a, aBase + k * 32);
#pragma unroll
        for (int j = 0; j < 8; j++) {
            uint32_t b[4];
            ldm_x4(b, bB[j] + k * 32);
            mma16816(c[2 * j],     a, b[0], b[1]);
            mma16816(c[2 * j + 1], a, b[2], b[3]);
        }
    }

    // epilogue: bias + leaky -> fp16 g_hn
    const long long rb = r0 + 16 * wid + (lane >> 2);
#pragma unroll
    for (int j = 0; j < 16; j++) {
        int col = 8 * j + 2 * (lane & 3);
        float2 bb = __ldg((const float2*)(bx + col));
#pragma unroll
        for (int r8 = 0; r8 < 2; r8++) {
            float v0 = c[j][2 * r8]     + bb.x;
            float v1 = c[j][2 * r8 + 1] + bb.y;
            v0 = fmaxf(v0, 0.01f * v0);
            v1 = fmaxf(v1, 0.01f * v1);
            *(uint32_t*)((char*)g_hn + ((rb + 8 * r8) * IN + col) * 2) = h2(v0, v1);
        }
    }
}

// ======================= edge MLP on fp16 mma.sync =========================
constexpr int ASTRB  = 560;                      // A row stride: 280 fp16
constexpr int OFF_W  = 128 * ASTRB;              // 71680 (3 pair-slots of 2*WCH)
constexpr int OFF_PT = OFF_W;                    // classifier partials (reuse)
constexpr int OFF_MB = OFF_W + 3 * 2 * WCH;      // 194560 (3 mbarriers)
constexpr int SMEM_E = OFF_MB + 64;              // 194624

__device__ __forceinline__ uint32_t chunk_buf(uint32_t sbase, int c) {
    int p = c >> 1;
    return sbase + OFF_W + (uint32_t)((p % 3) * (2 * WCH)) + (uint32_t)((c & 1) * WCH);
}
__device__ __forceinline__ void wait_pair(uint32_t sbase, int p) {
    mbar_wait(sbase + OFF_MB + (p % 3) * 8, (uint32_t)((p / 3) & 1));
}
__device__ __forceinline__ void fetch_pair(uint32_t sbase, int p) {
    int s = p % 3;
    uint32_t mb = sbase + OFF_MB + s * 8;
    uint32_t bytes = (2 * p + 1 < NCHUNK) ? 2 * WCH : WCH;
    mbar_expect_tx(mb, bytes);
    bulk_g2s(sbase + OFF_W + s * (2 * WCH), g_wpack + (size_t)(2 * p) * WCH, bytes, mb);
}

__global__ void __launch_bounds__(256, 1)
edge_hmma_kernel(const float* __restrict__ eattr,
                 const float* __restrict__ b0, const float* __restrict__ bmid,
                 const float* __restrict__ Wlast, const float* __restrict__ blast,
                 float* __restrict__ out, int E)
{
    extern __shared__ char smc[];
    const uint32_t sbase = smem_u32(smc);
    const int tid = threadIdx.x, wid = tid >> 5, lane = tid & 31;
    const int mg = wid >> 2, ng = wid & 3;        // 2 x 4 warp grid
    const int RB = 64 * mg, CB = 64 * ng;
    const long long e0 = (long long)blockIdx.x * 128;

    if (tid == 0)
        for (int i = 0; i < 3; i++) mbar_init(sbase + OFF_MB + i * 8, 1);
    __syncthreads();
    if (tid == 0)
        for (int p = 0; p < 3; p++) fetch_pair(sbase, p);

    // ---------------- gather ef -> A plane (fp16 copies) --------------------
    {
        int e = tid >> 1, half = tid & 1;
        long long ge = e0 + e;
        const uint4* hr4 = (const uint4*)(g_hn + (size_t)g_ei[ge] * IN);
        const uint4* hc4 = (const uint4*)(g_hn + (size_t)g_ei[(long long)E + ge] * IN);
        const float4* ea4 = (const float4*)(eattr + ge * EA);
        uint4* dst = (uint4*)(smc + e * ASTRB + half * 272);
        if (half == 0) {
#pragma unroll
            for (int g = 0; g < 16; g++) dst[g] = hr4[g];
            dst[16] = hc4[0];
        } else {
#pragma unroll
            for (int g = 0; g < 15; g++) dst[g] = hc4[1 + g];
#pragma unroll
            for (int g = 0; g < 2; g++) {
                float4 f0 = ea4[2 * g], f1 = ea4[2 * g + 1];
                uint4 u;
                u.x = h2(f0.x, f0.y); u.y = h2(f0.z, f0.w);
                u.z = h2(f1.x, f1.y); u.w = h2(f1.z, f1.w);
                dst[15 + g] = u;
            }
        }
    }
    __syncthreads();

    // ---------------- per-thread invariant addresses ------------------------
    const int i7 = lane & 7;
    const int rowOff  = ((lane >> 3) & 1) * 8 + i7;
    const int aColOff = (lane >= 16) ? 16 : 0;            // bytes
    uint32_t aB[4];
#pragma unroll
    for (int i = 0; i < 4; i++)
        aB[i] = sbase + (uint32_t)(RB + 16 * i + rowOff) * ASTRB + aColOff;
    const int nIdx  = CB + ((lane >= 16) ? 8 : 0) + i7;
    const int bkOff = ((lane >> 3) & 1) * 16;             // bytes
    uint32_t bB[4];
#pragma unroll
    for (int j = 0; j < 4; j++) bB[j] = (uint32_t)(nIdx + 16 * j) * 80 + bkOff;

    float c[4][8][4];
#pragma unroll
    for (int i = 0; i < 4; i++)
#pragma unroll
        for (int j = 0; j < 8; j++)
#pragma unroll
            for (int q = 0; q < 4; q++) c[i][j][q] = 0.f;

    // ---------------- pair-pipelined mainloop -------------------------------
    uint32_t bf0[4][4], bf1[4][4];
    int chunkIdx = 0;

    // prologue: wait pair 0, preload B(chunk 0, s0)
    wait_pair(sbase, 0);
#pragma unroll
    for (int j = 0; j < 4; j++) ldm_x4(bf0[j], chunk_buf(sbase, 0) + bB[j]);

#pragma unroll 1
    for (int L = 0; L < 9; L++) {
#pragma unroll 1
        for (int p = 0; p < 4; p++) {
            const int ca = chunkIdx, cb = ca + 1, nc = ca + 2;
            const int kA = p * 128;
            const uint32_t bufA = chunk_buf(sbase, ca);
            uint32_t a[4][4];

#pragma unroll
            for (int j = 0; j < 4; j++) ldm_x4(bf1[j], bufA + bB[j] + 32);
#pragma unroll
            for (int i = 0; i < 4; i++) ldm_x4(a[i], aB[i] + kA);
            mma_block(c, a, bf0);
            if ((cb & 1) == 0) wait_pair(sbase, cb >> 1);
            const uint32_t bufB = chunk_buf(sbase, cb);
#pragma unroll
            for (int i = 0; i < 4; i++) ldm_x4(a[i], aB[i] + kA + 32);
#pragma unroll
            for (int j = 0; j < 4; j++) ldm_x4(bf0[j], bufB + bB[j]);
            mma_block(c, a, bf1);
#pragma unroll
            for (int j = 0; j < 4; j++) ldm_x4(bf1[j], bufB + bB[j] + 32);
#pragma unroll
            for (int i = 0; i < 4; i++) ldm_x4(a[i], aB[i] + kA + 64);
            mma_block(c, a, bf0);
            const bool hn = nc < NCHUNK;
            if (hn && (nc & 1) == 0) wait_pair(sbase, nc >> 1);
#pragma unroll
            for (int i = 0; i < 4; i++) ldm_x4(a[i], aB[i] + kA + 96);
            if (hn) {
                const uint32_t bufN = chunk_buf(sbase, nc);
#pragma unroll
                for (int j = 0; j < 4; j++) ldm_x4(bf0[j], bufN + bB[j]);
            }
            mma_block(c, a, bf1);

            __syncthreads();
            if (tid == 0) {
                const int pn = (ca >> 1) + 3;
                if (2 * pn < NCHUNK) fetch_pair(sbase, pn);
            }
            chunkIdx += 2;
        }

        if (L == 0) {
            // tail chunk 8 (single k16 step); bf0 = B(8, s0). Pair 4 already
            // waited (at nc=8 of the previous iteration); chunk 9 is co-resident.
            uint32_t a[4][4];
#pragma unroll
            for (int i = 0; i < 4; i++) ldm_x4(a[i], aB[i] + 512);
            mma_block(c, a, bf0);
            const uint32_t buf9 = chunk_buf(sbase, 9);
#pragma unroll
            for (int j = 0; j < 4; j++) ldm_x4(bf0[j], buf9 + bB[j]);
            __syncthreads();
            chunkIdx = 9;
        }

        if (L < 8) {
            // epilogue: leaky(D + bias) -> fp16 -> A plane; zero C
            const float* bias = (L == 0) ? b0 : bmid + (L - 1) * 256;
#pragma unroll
            for (int i = 0; i < 4; i++) {
                const int row0 = RB + 16 * i + (lane >> 2);
#pragma unroll
                for (int j = 0; j < 8; j++) {
                    const int col = CB + 8 * j + 2 * (lane & 3);
                    float2 bb = __ldg((const float2*)(bias + col));
                    float v0 = c[i][j][0] + bb.x, v1 = c[i][j][1] + bb.y;
                    float v2 = c[i][j][2] + bb.x, v3 = c[i][j][3] + bb.y;
                    v0 = fmaxf(v0, 0.01f * v0); v1 = fmaxf(v1, 0.01f * v1);
                    v2 = fmaxf(v2, 0.01f * v2); v3 = fmaxf(v3, 0.01f * v3);
                    char* p0 = smc + row0 * ASTRB + col * 2;
                    *(uint32_t*)(p0)             = h2(v0, v1);
                    *(uint32_t*)(p0 + 8 * ASTRB) = h2(v2, v3);
                    c[i][j][0] = 0.f; c[i][j][1] = 0.f;
                    c[i][j][2] = 0.f; c[i][j][3] = 0.f;
                }
            }
            __syncthreads();
        }
    }

    // ---------------- classifier + log_softmax ------------------------------
    {
        const float* bias = bmid + 7 * 256;
        float p[4][2][3];
#pragma unroll
        for (int i = 0; i < 4; i++)
#pragma unroll
            for (int h = 0; h < 2; h++)
                p[i][h][0] = p[i][h][1] = p[i][h][2] = 0.f;
#pragma unroll
        for (int i = 0; i < 4; i++) {
#pragma unroll
            for (int j = 0; j < 8; j++) {
                const int col = CB + 8 * j + 2 * (lane & 3);
                float2 bb = __ldg((const float2*)(bias + col));
                float v0 = c[i][j][0] + bb.x, v1 = c[i][j][1] + bb.y;
                float v2 = c[i][j][2] + bb.x, v3 = c[i][j][3] + bb.y;
                v0 = fmaxf(v0, 0.01f * v0); v1 = fmaxf(v1, 0.01f * v1);
                v2 = fmaxf(v2, 0.01f * v2); v3 = fmaxf(v3, 0.01f * v3);
                const float* w0 = Wlast + col * 3;
#pragma unroll
                for (int k = 0; k < 3; k++) {
                    float wa = __ldg(w0 + k), wb2 = __ldg(w0 + 3 + k);
                    p[i][0][k] = fmaf(v0, wa, fmaf(v1, wb2, p[i][0][k]));
                    p[i][1][k] = fmaf(v2, wa, fmaf(v3, wb2, p[i][1][k]));
                }
            }
        }
#pragma unroll
        for (int i = 0; i < 4; i++)
#pragma unroll
            for (int h = 0; h < 2; h++)
#pragma unroll
                for (int k = 0; k < 3; k++) {
                    float v = p[i][h][k];
                    v += __shfl_xor_sync(0xffffffffu, v, 1);
                    v += __shfl_xor_sync(0xffffffffu, v, 2);
                    p[i][h][k] = v;
                }
        float* pt = (float*)(smc + OFF_PT);   // [128 rows][4 ng][3]
        if ((lane & 3) == 0) {
#pragma unroll
            for (int i = 0; i < 4; i++)
#pragma unroll
                for (int h = 0; h < 2; h++) {
                    int row = RB + 16 * i + (lane >> 2) + 8 * h;
#pragma unroll
                    for (int k = 0; k < 3; k++)
                        pt[(row * 4 + ng) * 3 + k] = p[i][h][k];
                }
        }
    }
    __syncthreads();
    if (tid < 128) {
        const float* pt = (const float*)(smc + OFF_PT);
        float l[3];
#pragma unroll
        for (int k = 0; k < 3; k++) {
            float s = __ldg(blast + k);
#pragma unroll
            for (int g = 0; g < 4; g++) s += pt[(tid * 4 + g) * 3 + k];
            l[k] = s;
        }
        float mx  = fmaxf(l[0], fmaxf(l[1], l[2]));
        float lse = mx + logf(expf(l[0] - mx) + expf(l[1] - mx) + expf(l[2] - mx));
        float* o = out + (e0 + tid) * NOUT;
        o[0] = l[0] - lse; o[1] = l[1] - lse; o[2] = l[2] - lse;
    }
}

// ===========================================================================
extern "C" void kernel_launch(void* const* d_in, const int* in_sizes, int n_in,
                              void* d_out, int out_size)
{
    const float* x      = (const float*)d_in[0];
    const int*   ei_raw = (const int*)d_in[1];
    const float* eattr  = (const float*)d_in[2];
    const float* Wx     = (const float*)d_in[3];
    const float* bx     = (const float*)d_in[4];
    const float* W0     = (const float*)d_in[5];
    const float* b0     = (const float*)d_in[6];
    const float* Wmid   = (const float*)d_in[7];
    const float* bmid   = (const float*)d_in[8];
    const float* Wlast  = (const float*)d_in[9];
    const float* blast  = (const float*)d_in[10];
    float* out = (float*)d_out;

    const int N  = in_sizes[0] / DN;
    const int E  = in_sizes[2] / EA;
    const int n2 = 2 * E;
    const int nconv = (n2 + 255) / 256;

    cudaFuncSetAttribute(node_hmma_kernel,
                         cudaFuncAttributeMaxDynamicSharedMemorySize, SMEM_N);
    cudaFuncSetAttribute(edge_hmma_kernel,
                         cudaFuncAttributeMaxDynamicSharedMemorySize, SMEM_E);

    prep_all<<<nconv + NPACK_BLK + NWX_BLK, 256>>>(ei_raw, W0, Wmid, Wx, n2);
    node_hmma_kernel<<<N / 64, 128, SMEM_N>>>(x, bx);
    edge_hmma_kernel<<<E / 128, 256, SMEM_E>>>(eattr, b0, bmid, Wlast, blast,
                                               out, E);
}